// round 13
// baseline (speedup 1.0000x reference)
#include <cuda_runtime.h>
#include <cuda_fp16.h>
#include <math.h>
#include <stdint.h>

#define BB  2
#define SS  2048
#define DD  1024
#define HH  16
#define DKK 64
#define MM  (BB*SS)   // 4096 rows

// scale folded into Q: 1/sqrt(64) * log2(e)
#define SC2 0.18033688011112042f

// ---------------------------------------------------------------------------
// Scratch (allocation-free rule: __device__ globals)
// ---------------------------------------------------------------------------
__device__ __align__(16) float g_PE[SS*DKK];
__device__ __align__(16) float g_Kraw[MM*DD];
__device__ __align__(16) float g_Y[MM*DD];

__device__ __align__(16) __half g_Xh[MM*DD];
__device__ __align__(16) __half g_Wh[3*DD*DD];
__device__ __align__(16) __half g_Woh[DD*DD];
__device__ __align__(16) __half g_Ah[MM*DD];

// attention operands, head-split [B*H][S][64]
__device__ __align__(16) __half g_Qh[MM*DD];
__device__ __align__(16) __half g_Kh[MM*DD];
__device__ __align__(16) __half g_Vh[MM*DD];

// ---------------------------------------------------------------------------
// PTX helpers (baseline sm_103-safe)
// ---------------------------------------------------------------------------
__device__ __forceinline__ uint32_t smem_u32(const void* p) {
    uint32_t a;
    asm("{ .reg .u64 t; cvta.to.shared.u64 t, %1; cvt.u32.u64 %0, t; }"
        : "=r"(a) : "l"(p));
    return a;
}

#define CPA16(dst, src) \
    asm volatile("cp.async.cg.shared.global [%0], [%1], 16;" :: "r"(dst), "l"(src) : "memory")
#define CPA_COMMIT() asm volatile("cp.async.commit_group;" ::: "memory")
#define CPA_WAIT1()  asm volatile("cp.async.wait_group 1;" ::: "memory")
#define CPA_WAIT0()  asm volatile("cp.async.wait_group 0;" ::: "memory")

__device__ __forceinline__ void ldsm_x4(uint32_t* r, uint32_t addr) {
    asm volatile("ldmatrix.sync.aligned.m8n8.x4.shared.b16 {%0,%1,%2,%3}, [%4];"
                 : "=r"(r[0]), "=r"(r[1]), "=r"(r[2]), "=r"(r[3]) : "r"(addr));
}
__device__ __forceinline__ void ldsm_x4_t(uint32_t* r, uint32_t addr) {
    asm volatile("ldmatrix.sync.aligned.m8n8.x4.trans.shared.b16 {%0,%1,%2,%3}, [%4];"
                 : "=r"(r[0]), "=r"(r[1]), "=r"(r[2]), "=r"(r[3]) : "r"(addr));
}

__device__ __forceinline__ void mma_f16(float* c, const uint32_t* a, const uint32_t* b) {
    asm volatile(
        "mma.sync.aligned.m16n8k16.row.col.f32.f16.f16.f32 "
        "{%0,%1,%2,%3}, {%4,%5,%6,%7}, {%8,%9}, {%0,%1,%2,%3};"
        : "+f"(c[0]), "+f"(c[1]), "+f"(c[2]), "+f"(c[3])
        : "r"(a[0]), "r"(a[1]), "r"(a[2]), "r"(a[3]), "r"(b[0]), "r"(b[1]));
}

__device__ __forceinline__ float ex2(float x) {
    float r;
    asm("ex2.approx.ftz.f32 %0, %1;" : "=f"(r) : "f"(x));
    return r;
}

// ---------------------------------------------------------------------------
// prep: convx (blocks 0..4095) + convw (4096..8191) + pe (8192..8703)
// ---------------------------------------------------------------------------
__global__ void prep_kernel(const float* __restrict__ X,
                            const float* __restrict__ Wq, const float* __restrict__ Wk,
                            const float* __restrict__ Wv, const float* __restrict__ Wo) {
    int bid = blockIdx.x;
    int t   = threadIdx.x;
    if (bid < 4096) {
        int i = bid * 256 + t;                 // MM*DD/4
        float4 v = ((const float4*)X)[i];
        __half2* hp = (__half2*)g_Xh;
        hp[2*i]   = __floats2half2_rn(v.x, v.y);
        hp[2*i+1] = __floats2half2_rn(v.z, v.w);
    } else if (bid < 8192) {
        int gi  = (bid - 4096) * 256 + t;      // 4 * DD*DD/4
        int mat = gi >> 18;
        int i   = gi & 0x3FFFF;
        const float* src = (mat == 0) ? Wq : (mat == 1) ? Wk : (mat == 2) ? Wv : Wo;
        __half2* hp = (mat < 3) ? (__half2*)(g_Wh + (size_t)mat * DD * DD)
                                : (__half2*)g_Woh;
        float4 v = ((const float4*)src)[i];
        hp[2*i]   = __floats2half2_rn(v.x, v.y);
        hp[2*i+1] = __floats2half2_rn(v.z, v.w);
    } else {
        int idx = (bid - 8192) * 256 + t;      // SS*DKK = 131072
        int s  = idx >> 6;
        int dk = idx & 63;
        int i  = dk >> 1;
        float freq = expf(-((float)(2 * i) / 64.0f) * 9.210340371976184f);
        float ang  = (float)s * freq;
        g_PE[idx]  = (dk & 1) ? cosf(ang) : sinf(ang);
    }
}

// ---------------------------------------------------------------------------
// fp16 single-pass HMMA GEMM: 128 threads, 64x64 warp tiles (2x2 warp grid),
// BK=64 (16 iterations), 3-stage cp.async pipeline, swizzled 128B rows
// (chunk ^= row&7 -> conflict-free ldsm phases and stores).
// ---------------------------------------------------------------------------
#define MATB 16384           // 128 rows * 128 B
#define STG  (2 * MATB)      // 32768
#define DYN_SMEM (3 * STG)   // 98304

__device__ __forceinline__ void mma_gemm(
    const __half* __restrict__ A, const __half* __restrict__ B,
    char* dyn, float acc[4][8][4])
{
    int t    = threadIdx.x;
    int lane = t & 31;
    int wid  = t >> 5;
    int wm   = wid & 1;
    int wn   = wid >> 1;
    uint32_t sbase = smem_u32(dyn);

    const char* mats[2] = {(const char*)A, (const char*)B};

#pragma unroll
    for (int tm = 0; tm < 4; tm++)
#pragma unroll
        for (int tn = 0; tn < 8; tn++)
#pragma unroll
            for (int u = 0; u < 4; u++) acc[tm][tn][u] = 0.0f;

    // copy: 2048 16B-chunks per stage, 16 per thread
    int idx0 = t * 16;
    auto load_stage = [&](int st, int kb) {
        uint32_t stb = sbase + st * STG;
#pragma unroll
        for (int q = 0; q < 16; q++) {
            int idx = idx0 + q;
            int mat = idx >> 10;             // 1024 chunks per mat
            int r   = (idx >> 3) & 127;
            int c   = idx & 7;
            uint32_t dst = stb + mat * MATB + r * 128 + ((c ^ (r & 7)) << 4);
            const char* src = mats[mat] + ((size_t)r * 1024 + kb + c * 8) * 2;
            CPA16(dst, src);
        }
        CPA_COMMIT();
    };

    int a_hi = lane >> 4;
    int b_hi = (lane >> 3) & 1;
    uint32_t aOff[4]; int aMsk[4];
#pragma unroll
    for (int tm = 0; tm < 4; tm++) {
        int r = wm * 64 + (lane & 15) + 16 * tm;
        aOff[tm] = (uint32_t)(r * 128);
        aMsk[tm] = r & 7;
    }
    uint32_t bOff[4]; int bMsk[4];
#pragma unroll
    for (int tp = 0; tp < 4; tp++) {
        int r = wn * 64 + (lane & 7) + 8 * (lane >> 4) + 16 * tp;
        bOff[tp] = (uint32_t)(r * 128);
        bMsk[tp] = r & 7;
    }

    load_stage(0, 0);
    load_stage(1, 64);

    int st = 0;
    for (int it = 0; it < 16; it++) {
        if (it < 15) { CPA_WAIT1(); } else { CPA_WAIT0(); }
        __syncthreads();
        if (it + 2 < 16) {
            int s2 = st + 2; if (s2 >= 3) s2 -= 3;
            load_stage(s2, (it + 2) * 64);
        }

        uint32_t stb = sbase + st * STG;
#pragma unroll
        for (int ks = 0; ks < 4; ks++) {
            int cA = 2 * ks + a_hi;
            int cB = 2 * ks + b_hi;
            uint32_t aF[4][4], bF[8][2];
#pragma unroll
            for (int tm = 0; tm < 4; tm++) {
                uint32_t off = aOff[tm] + (uint32_t)((cA ^ aMsk[tm]) << 4);
                ldsm_x4(aF[tm], stb + 0 * MATB + off);
            }
#pragma unroll
            for (int tp = 0; tp < 4; tp++) {
                uint32_t off = bOff[tp] + (uint32_t)((cB ^ bMsk[tp]) << 4);
                ldsm_x4(&bF[2 * tp][0], stb + 1 * MATB + off);
            }
#pragma unroll
            for (int tm = 0; tm < 4; tm++)
#pragma unroll
                for (int tn = 0; tn < 8; tn++)
                    mma_f16(acc[tm][tn], aF[tm], bF[tn]);
        }
        st++; if (st == 3) st = 0;
    }
    __syncthreads();
}

// ---------------------------------------------------------------------------
// QKV GEMM. z=0: Q -> (acc+PE)*SC2 fp16; z=1: K fp32; z=2: V fp16
// ---------------------------------------------------------------------------
__global__ __launch_bounds__(128, 2) void qkv_mma() {
    extern __shared__ char dyn[];
    float acc[4][8][4];

    int z  = blockIdx.z;
    int m0 = blockIdx.y * 128;
    int n0 = blockIdx.x * 128;

    mma_gemm(g_Xh + (size_t)m0 * 1024,
             g_Wh + (size_t)z * DD * DD + (size_t)n0 * 1024,
             dyn, acc);

    int t = threadIdx.x, lane = t & 31, wid = t >> 5;
    int wm = wid & 1, wn = wid >> 1;

#pragma unroll
    for (int tm = 0; tm < 4; tm++)
#pragma unroll
        for (int tn = 0; tn < 8; tn++) {
            int c  = n0 + wn * 64 + tn * 8 + (lane & 3) * 2;
            int h  = c >> 6, dk = c & 63;
#pragma unroll
            for (int half = 0; half < 2; half++) {
                int m = m0 + wm * 64 + tm * 16 + (lane >> 2) + 8 * half;
                int b = m >> 11, s = m & 2047;
                float vx = acc[tm][tn][2 * half + 0];
                float vy = acc[tm][tn][2 * half + 1];
                size_t off = ((size_t)((b * 16 + h) * 2048 + s)) * 64 + dk;
                if (z == 1) {
                    float2 v; v.x = vx; v.y = vy;
                    *(float2*)&g_Kraw[off] = v;
                } else if (z == 2) {
                    ((__half2*)g_Vh)[off >> 1] = __floats2half2_rn(vx, vy);
                } else {
                    float2 pe = *(const float2*)&g_PE[s * 64 + dk];
                    vx = (vx + pe.x) * SC2;
                    vy = (vy + pe.y) * SC2;
                    ((__half2*)g_Qh)[off >> 1] = __floats2half2_rn(vx, vy);
                }
            }
        }
}

// ---------------------------------------------------------------------------
// EMA smear on K + PE add, output fp16
// ---------------------------------------------------------------------------
__global__ void smear_kernel(const float* __restrict__ alpha) {
    int idx = blockIdx.x * blockDim.x + threadIdx.x;
    int dk = idx & 63;
    int s  = (idx >> 6) & 2047;
    int h  = (idx >> 17) & 15;
    float kc = g_Kraw[idx];
    float v;
    if (s == 0) {
        v = kc;
    } else {
        float a = 1.0f / (1.0f + expf(-alpha[h * 2047 + (s - 1)]));
        v = a * kc + (1.0f - a) * g_Kraw[idx - 64];
    }
    v += g_PE[s * 64 + dk];
    g_Kh[idx] = __float2half_rn(v);
}

// ---------------------------------------------------------------------------
// Causal flash attention, fp16 HMMA. BM=128 (8 warps, 256 thr), BN=64.
// 2-stage double-buffered KV pipeline (proven R12, unchanged).
// ---------------------------------------------------------------------------
#define ASTR 144
#define AMAT (64 * ASTR)    // 9216
#define KVSTG (2 * AMAT)    // 18432 per stage

__global__ __launch_bounds__(256, 2) void attn_mma() {
    __shared__ __align__(16) char sm[2 * KVSTG];
    uint32_t sb = smem_u32(sm);

    int t = threadIdx.x, lane = t & 31, w = t >> 5;   // w = 0..7
    int qt = 15 - (int)blockIdx.x;          // heavy tiles first
    int qb = qt * 128;
    int bh = blockIdx.y;
    size_t base = (size_t)bh * SS * DKK;

    // ---- stage Q tile, extract frags ----
    {
        const char* qsrc = (const char*)(g_Qh + base);
#pragma unroll
        for (int q = 0; q < 4; q++) {
            int idx = t * 4 + q;
            int r   = idx >> 3;
            int c   = idx & 7;
            CPA16(sb + r * ASTR + c * 16,
                  qsrc + ((size_t)(qb + r) * 64 + c * 8) * 2);
        }
        CPA_COMMIT(); CPA_WAIT0();
        __syncthreads();
    }

    uint32_t qF[4][4];
    {
        int ar = w * 16 + (lane & 15);
#pragma unroll
        for (int k = 0; k < 4; k++) {
            uint32_t acol = (uint32_t)(k * 32 + (lane >> 4) * 16);
            ldsm_x4(qF[k], sb + ar * ASTR + acol);
        }
    }
    __syncthreads();

    float o[8][4];
    float m2[2], lsum[2];
#pragma unroll
    for (int j = 0; j < 8; j++)
#pragma unroll
        for (int u = 0; u < 4; u++) o[j][u] = 0.0f;
    m2[0] = m2[1] = -1e30f;
    lsum[0] = lsum[1] = 0.0f;

    const char* kvsrc[2] = {(const char*)(g_Kh + base), (const char*)(g_Vh + base)};

    auto load_kv = [&](int tile, int st) {
        uint32_t stb = sb + st * KVSTG;
        int kb = tile * 64;
#pragma unroll
        for (int q = 0; q < 4; q++) {
            int idx = t * 4 + q;
            int mat = idx >> 9;
            int r   = (idx >> 3) & 63;
            int c   = idx & 7;
            CPA16(stb + mat * AMAT + r * ASTR + c * 16,
                  kvsrc[mat] + ((size_t)(kb + r) * 64 + c * 8) * 2);
        }
        CPA_COMMIT();
    };

    int r0 = (lane >> 2);
    int ntiles = 2 * qt + 2;

    load_kv(0, 0);
    if (ntiles > 1) load_kv(1, 1);

    for (int tile = 0; tile < ntiles; tile++) {
        int kb = tile * 64;
        int st = tile & 1;
        if (tile + 1 < ntiles) { CPA_WAIT1(); } else { CPA_WAIT0(); }
        __syncthreads();

        uint32_t stb = sb + st * KVSTG;
        bool active = (kb <= qb + w * 16 + 15);

        if (active) {
            float s[8][4];
#pragma unroll
            for (int j = 0; j < 8; j++)
#pragma unroll
                for (int u = 0; u < 4; u++) s[j][u] = 0.0f;

            {
                int b_row = (lane & 7) + 8 * (lane >> 4);
#pragma unroll
                for (int k = 0; k < 4; k++) {
                    uint32_t bcol = (uint32_t)((k * 16 + 8 * ((lane >> 3) & 1)) * 2);
                    uint32_t kF[8][2];
#pragma unroll
                    for (int tp = 0; tp < 4; tp++) {
                        uint32_t off = (uint32_t)((b_row + 16 * tp) * ASTR) + bcol;
                        ldsm_x4(&kF[2 * tp][0], stb + 0 * AMAT + off);
                    }
#pragma unroll
                    for (int j = 0; j < 8; j++) mma_f16(s[j], qF[k], kF[j]);
                }
            }

            if (kb + 63 > qb + w * 16) {
#pragma unroll
                for (int j = 0; j < 8; j++)
#pragma unroll
                    for (int u = 0; u < 4; u++) {
                        int row = qb + w * 16 + r0 + 8 * (u >> 1);
                        int col = kb + j * 8 + 2 * (lane & 3) + (u & 1);
                        if (col > row) s[j][u] = -1e30f;
                    }
            }

#pragma unroll
            for (int h = 0; h < 2; h++) {
                float mx = -1e30f;
#pragma unroll
                for (int j = 0; j < 8; j++) {
                    mx = fmaxf(mx, s[j][2 * h + 0]);
                    mx = fmaxf(mx, s[j][2 * h + 1]);
                }
                mx = fmaxf(mx, __shfl_xor_sync(0xffffffffu, mx, 1));
                mx = fmaxf(mx, __shfl_xor_sync(0xffffffffu, mx, 2));
                float mnew = fmaxf(m2[h], mx);
                float corr = ex2(m2[h] - mnew);
                m2[h] = mnew;
                float rs = 0.0f;
#pragma unroll
                for (int j = 0; j < 8; j++) {
                    float p0 = ex2(s[j][2 * h + 0] - mnew);
                    float p1 = ex2(s[j][2 * h + 1] - mnew);
                    s[j][2 * h + 0] = p0;
                    s[j][2 * h + 1] = p1;
                    rs += p0 + p1;
                }
                lsum[h] = lsum[h] * corr + rs;
#pragma unroll
                for (int j = 0; j < 8; j++) {
                    o[j][2 * h + 0] *= corr;
                    o[j][2 * h + 1] *= corr;
                }
            }

            uint32_t pF[4][4];
#pragma unroll
            for (int kk = 0; kk < 4; kk++) {
                int j = 2 * kk;
#pragma unroll
                for (int q = 0; q < 4; q++) {
                    int jj = j + (q >> 1);
                    __half2 hp = __floats2half2_rn(s[jj][(q & 1) * 2 + 0],
                                                   s[jj][(q & 1) * 2 + 1]);
                    pF[kk][q] = *(uint32_t*)&hp;
                }
            }

            {
                int vrow = (lane & 7) + 8 * ((lane >> 3) & 1);
                uint32_t vcol = (uint32_t)(16 * (lane >> 4));
#pragma unroll
                for (int kk = 0; kk < 4; kk++) {
                    uint32_t vF[8][2];
#pragma unroll
                    for (int jj = 0; jj < 4; jj++) {
                        uint32_t off = (uint32_t)((kk * 16 + vrow) * ASTR) + (uint32_t)(jj * 32) + vcol;
                        ldsm_x4_t(&vF[2 * jj][0], stb + 1 * AMAT + off);
                    }
#pragma unroll
                    for (int j = 0; j < 8; j++) mma_f16(o[j], pF[kk], vF[j]);
                }
            }
        }

        __syncthreads();
        if (tile + 2 < ntiles) load_kv(tile + 2, st);
    }

#pragma unroll
    for (int h = 0; h < 2; h++) {
        lsum[h] += __shfl_xor_sync(0xffffffffu, lsum[h], 1);
        lsum[h] += __shfl_xor_sync(0xffffffffu, lsum[h], 2);
        lsum[h] = 1.0f / lsum[h];
    }

    int b = bh >> 4, hh = bh & 15;
#pragma unroll
    for (int j = 0; j < 8; j++) {
        int dk = j * 8 + 2 * (lane & 3);
#pragma unroll
        for (int h = 0; h < 2; h++) {
            int srow = qb + w * 16 + r0 + 8 * h;
            float f0 = o[j][2 * h + 0] * lsum[h];
            float f1 = o[j][2 * h + 1] * lsum[h];
            size_t off = ((size_t)(b * SS + srow) * DD + hh * 64 + dk) >> 1;
            ((__half2*)g_Ah)[off] = __floats2half2_rn(f0, f1);
        }
    }
}

// ---------------------------------------------------------------------------
// Output projection GEMM: Y = attn @ Wo^T + X
// ---------------------------------------------------------------------------
__global__ __launch_bounds__(128, 2) void oproj_mma(const float* __restrict__ X) {
    extern __shared__ char dyn[];
    float acc[4][8][4];

    int m0 = blockIdx.y * 128;
    int n0 = blockIdx.x * 128;

    mma_gemm(g_Ah + (size_t)m0 * 1024, g_Woh + (size_t)n0 * 1024, dyn, acc);

    int t = threadIdx.x, lane = t & 31, wid = t >> 5;
    int wm = wid & 1, wn = wid >> 1;
#pragma unroll
    for (int tm = 0; tm < 4; tm++)
#pragma unroll
        for (int tn = 0; tn < 8; tn++) {
            int c = n0 + wn * 64 + tn * 8 + (lane & 3) * 2;
#pragma unroll
            for (int half = 0; half < 2; half++) {
                int m = m0 + wm * 64 + tm * 16 + (lane >> 2) + 8 * half;
                float2 xr = *(const float2*)&X[(size_t)m * 1024 + c];
                float2 v;
                v.x = acc[tm][tn][2 * half + 0] + xr.x;
                v.y = acc[tm][tn][2 * half + 1] + xr.y;
                *(float2*)&g_Y[(size_t)m * 1024 + c] = v;
            }
        }
}

// ---------------------------------------------------------------------------
// LayerNorm over D=1024 per row
// ---------------------------------------------------------------------------
__global__ void ln_kernel(const float* __restrict__ gamma,
                          const float* __restrict__ beta,
                          float* __restrict__ out)
{
    int row = blockIdx.x;
    int t   = threadIdx.x;
    const float* y = g_Y + (size_t)row * 1024;

    float x[4];
    float s = 0.0f;
#pragma unroll
    for (int u = 0; u < 4; u++) { x[u] = y[t + 256 * u]; s += x[u]; }

    __shared__ float red[32];
#pragma unroll
    for (int off = 16; off; off >>= 1) s += __shfl_xor_sync(0xffffffffu, s, off);
    if ((t & 31) == 0) red[t >> 5] = s;
    __syncthreads();
    if (t == 0) {
        float tot = 0.0f;
        for (int w = 0; w < 8; w++) tot += red[w];
        red[8] = tot;
    }
    __syncthreads();
    float mean = red[8] * (1.0f / 1024.0f);

    float vs = 0.0f;
#pragma unroll
    for (int u = 0; u < 4; u++) { float d = x[u] - mean; vs += d * d; }
#pragma unroll
    for (int off = 16; off; off >>= 1) vs += __shfl_xor_sync(0xffffffffu, vs, off);
    if ((t & 31) == 0) red[16 + (t >> 5)] = vs;
    __syncthreads();
    if (t == 0) {
        float tot = 0.0f;
        for (int w = 0; w < 8; w++) tot += red[16 + w];
        red[24] = tot;
    }
    __syncthreads();
    float var  = red[24] * (1.0f / 1024.0f);
    float rstd = rsqrtf(var + 1e-5f);

#pragma unroll
    for (int u = 0; u < 4; u++) {
        int c = t + 256 * u;
        out[(size_t)row * 1024 + c] = (x[u] - mean) * rstd * gamma[c] + beta[c];
    }
}

// ---------------------------------------------------------------------------
extern "C" void kernel_launch(void* const* d_in, const int* in_sizes, int n_in,
                              void* d_out, int out_size)
{
    const float* X     = (const float*)d_in[0];
    const float* Wq    = (const float*)d_in[1];
    const float* Wk    = (const float*)d_in[2];
    const float* Wv    = (const float*)d_in[3];
    const float* Wo    = (const float*)d_in[4];
    const float* alpha = (const float*)d_in[5];
    const float* lns   = (const float*)d_in[6];
    const float* lnb   = (const float*)d_in[7];
    float* out = (float*)d_out;

    static int attr_set = 0;
    if (!attr_set) {
        cudaFuncSetAttribute(qkv_mma,   cudaFuncAttributeMaxDynamicSharedMemorySize, DYN_SMEM);
        cudaFuncSetAttribute(oproj_mma, cudaFuncAttributeMaxDynamicSharedMemorySize, DYN_SMEM);
        attr_set = 1;
    }

    prep_kernel<<<8704, 256>>>(X, Wq, Wk, Wv, Wo);                 // 1
    qkv_mma<<<dim3(8, 32, 3), 128, DYN_SMEM>>>();                  // 2
    smear_kernel<<<(MM * DD) / 256, 256>>>(alpha);                 // 3
    attn_mma<<<dim3(16, 32), 256>>>();                             // 4
    oproj_mma<<<dim3(8, 32), 128, DYN_SMEM>>>(X);                  // 5
    ln_kernel<<<MM, 256>>>(lns, lnb, out);                         // 6
}

// round 14
// speedup vs baseline: 1.0840x; 1.0840x over previous
#include <cuda_runtime.h>
#include <cuda_fp16.h>
#include <math.h>
#include <stdint.h>

#define BB  2
#define SS  2048
#define DD  1024
#define HH  16
#define DKK 64
#define MM  (BB*SS)   // 4096 rows

// scale folded into Q: 1/sqrt(64) * log2(e)
#define SC2 0.18033688011112042f

// ---------------------------------------------------------------------------
// Scratch (allocation-free rule: __device__ globals)
// ---------------------------------------------------------------------------
__device__ __align__(16) float g_PE[SS*DKK];
__device__ __align__(16) float g_Kraw[MM*DD];
__device__ __align__(16) float g_Y[MM*DD];

__device__ __align__(16) __half g_Xh[MM*DD];
__device__ __align__(16) __half g_Wh[3*DD*DD];
__device__ __align__(16) __half g_Woh[DD*DD];
__device__ __align__(16) __half g_Ah[MM*DD];

// attention operands, head-split [B*H][S][64]
__device__ __align__(16) __half g_Qh[MM*DD];
__device__ __align__(16) __half g_Kh[MM*DD];
__device__ __align__(16) __half g_Vh[MM*DD];

// ---------------------------------------------------------------------------
// PTX helpers (baseline sm_103-safe)
// ---------------------------------------------------------------------------
__device__ __forceinline__ uint32_t smem_u32(const void* p) {
    uint32_t a;
    asm("{ .reg .u64 t; cvta.to.shared.u64 t, %1; cvt.u32.u64 %0, t; }"
        : "=r"(a) : "l"(p));
    return a;
}

#define CPA16(dst, src) \
    asm volatile("cp.async.cg.shared.global [%0], [%1], 16;" :: "r"(dst), "l"(src) : "memory")
#define CPA_COMMIT() asm volatile("cp.async.commit_group;" ::: "memory")
#define CPA_WAIT1()  asm volatile("cp.async.wait_group 1;" ::: "memory")
#define CPA_WAIT0()  asm volatile("cp.async.wait_group 0;" ::: "memory")

__device__ __forceinline__ void ldsm_x4(uint32_t* r, uint32_t addr) {
    asm volatile("ldmatrix.sync.aligned.m8n8.x4.shared.b16 {%0,%1,%2,%3}, [%4];"
                 : "=r"(r[0]), "=r"(r[1]), "=r"(r[2]), "=r"(r[3]) : "r"(addr));
}
__device__ __forceinline__ void ldsm_x4_t(uint32_t* r, uint32_t addr) {
    asm volatile("ldmatrix.sync.aligned.m8n8.x4.trans.shared.b16 {%0,%1,%2,%3}, [%4];"
                 : "=r"(r[0]), "=r"(r[1]), "=r"(r[2]), "=r"(r[3]) : "r"(addr));
}

__device__ __forceinline__ void mma_f16(float* c, const uint32_t* a, const uint32_t* b) {
    asm volatile(
        "mma.sync.aligned.m16n8k16.row.col.f32.f16.f16.f32 "
        "{%0,%1,%2,%3}, {%4,%5,%6,%7}, {%8,%9}, {%0,%1,%2,%3};"
        : "+f"(c[0]), "+f"(c[1]), "+f"(c[2]), "+f"(c[3])
        : "r"(a[0]), "r"(a[1]), "r"(a[2]), "r"(a[3]), "r"(b[0]), "r"(b[1]));
}

__device__ __forceinline__ float ex2(float x) {
    float r;
    asm("ex2.approx.ftz.f32 %0, %1;" : "=f"(r) : "f"(x));
    return r;
}

// ---------------------------------------------------------------------------
// prep: convx (blocks 0..4095) + convw (4096..8191) + pe (8192..8703)
// ---------------------------------------------------------------------------
__global__ void prep_kernel(const float* __restrict__ X,
                            const float* __restrict__ Wq, const float* __restrict__ Wk,
                            const float* __restrict__ Wv, const float* __restrict__ Wo) {
    int bid = blockIdx.x;
    int t   = threadIdx.x;
    if (bid < 4096) {
        int i = bid * 256 + t;                 // MM*DD/4
        float4 v = ((const float4*)X)[i];
        __half2* hp = (__half2*)g_Xh;
        hp[2*i]   = __floats2half2_rn(v.x, v.y);
        hp[2*i+1] = __floats2half2_rn(v.z, v.w);
    } else if (bid < 8192) {
        int gi  = (bid - 4096) * 256 + t;      // 4 * DD*DD/4
        int mat = gi >> 18;
        int i   = gi & 0x3FFFF;
        const float* src = (mat == 0) ? Wq : (mat == 1) ? Wk : (mat == 2) ? Wv : Wo;
        __half2* hp = (mat < 3) ? (__half2*)(g_Wh + (size_t)mat * DD * DD)
                                : (__half2*)g_Woh;
        float4 v = ((const float4*)src)[i];
        hp[2*i]   = __floats2half2_rn(v.x, v.y);
        hp[2*i+1] = __floats2half2_rn(v.z, v.w);
    } else {
        int idx = (bid - 8192) * 256 + t;      // SS*DKK = 131072
        int s  = idx >> 6;
        int dk = idx & 63;
        int i  = dk >> 1;
        float freq = expf(-((float)(2 * i) / 64.0f) * 9.210340371976184f);
        float ang  = (float)s * freq;
        g_PE[idx]  = (dk & 1) ? cosf(ang) : sinf(ang);
    }
}

// ---------------------------------------------------------------------------
// fp16 single-pass HMMA GEMM (proven R11/R12 config): 128 threads,
// 64x64 warp tiles, BK=32 (32 iters), 3-stage cp.async, swizzled 64B rows.
// ---------------------------------------------------------------------------
#define MATB 8192            // 128 * 64
#define STG  (2 * MATB)      // 16384
#define DYN_SMEM (3 * STG)   // 49152

__device__ __forceinline__ void mma_gemm(
    const __half* __restrict__ A, const __half* __restrict__ B,
    char* dyn, float acc[4][8][4])
{
    int t    = threadIdx.x;
    int lane = t & 31;
    int wid  = t >> 5;
    int wm   = wid & 1;
    int wn   = wid >> 1;
    uint32_t sbase = smem_u32(dyn);

    const char* mats[2] = {(const char*)A, (const char*)B};

#pragma unroll
    for (int tm = 0; tm < 4; tm++)
#pragma unroll
        for (int tn = 0; tn < 8; tn++)
#pragma unroll
            for (int u = 0; u < 4; u++) acc[tm][tn][u] = 0.0f;

    int idx0 = t * 8;
    auto load_stage = [&](int st, int kb) {
        uint32_t stb = sbase + st * STG;
#pragma unroll
        for (int q = 0; q < 8; q++) {
            int idx = idx0 + q;
            int mat = idx >> 9;
            int r   = (idx >> 2) & 127;
            int c   = idx & 3;
            uint32_t dst = stb + mat * MATB + r * 64 + ((c ^ ((r >> 1) & 3)) << 4);
            const char* src = mats[mat] + ((size_t)r * 1024 + kb + c * 8) * 2;
            CPA16(dst, src);
        }
        CPA_COMMIT();
    };

    int a_hi = lane >> 4;
    int b_hi = (lane >> 3) & 1;
    uint32_t aOff[4]; int aMsk[4];
#pragma unroll
    for (int tm = 0; tm < 4; tm++) {
        int r = wm * 64 + (lane & 15) + 16 * tm;
        aOff[tm] = (uint32_t)(r * 64);
        aMsk[tm] = (r >> 1) & 3;
    }
    uint32_t bOff[4]; int bMsk[4];
#pragma unroll
    for (int tp = 0; tp < 4; tp++) {
        int r = wn * 64 + (lane & 7) + 8 * (lane >> 4) + 16 * tp;
        bOff[tp] = (uint32_t)(r * 64);
        bMsk[tp] = (r >> 1) & 3;
    }

    load_stage(0, 0);
    load_stage(1, 32);

    int st = 0;
    for (int it = 0; it < 32; it++) {
        if (it < 31) { CPA_WAIT1(); } else { CPA_WAIT0(); }
        __syncthreads();
        if (it + 2 < 32) {
            int s2 = st + 2; if (s2 >= 3) s2 -= 3;
            load_stage(s2, (it + 2) * 32);
        }

        uint32_t stb = sbase + st * STG;
#pragma unroll
        for (int ks = 0; ks < 2; ks++) {
            int cA = 2 * ks + a_hi;
            int cB = 2 * ks + b_hi;
            uint32_t aF[4][4], bF[8][2];
#pragma unroll
            for (int tm = 0; tm < 4; tm++) {
                uint32_t off = aOff[tm] + (uint32_t)((cA ^ aMsk[tm]) << 4);
                ldsm_x4(aF[tm], stb + 0 * MATB + off);
            }
#pragma unroll
            for (int tp = 0; tp < 4; tp++) {
                uint32_t off = bOff[tp] + (uint32_t)((cB ^ bMsk[tp]) << 4);
                ldsm_x4(&bF[2 * tp][0], stb + 1 * MATB + off);
            }
#pragma unroll
            for (int tm = 0; tm < 4; tm++)
#pragma unroll
                for (int tn = 0; tn < 8; tn++)
                    mma_f16(acc[tm][tn], aF[tm], bF[tn]);
        }
        st++; if (st == 3) st = 0;
    }
    __syncthreads();
}

// ---------------------------------------------------------------------------
// QKV GEMM. z=0: Q -> (acc+PE)*SC2 fp16; z=1: K fp32; z=2: V fp16
// ---------------------------------------------------------------------------
__global__ __launch_bounds__(128, 2) void qkv_mma() {
    extern __shared__ char dyn[];
    float acc[4][8][4];

    int z  = blockIdx.z;
    int m0 = blockIdx.y * 128;
    int n0 = blockIdx.x * 128;

    mma_gemm(g_Xh + (size_t)m0 * 1024,
             g_Wh + (size_t)z * DD * DD + (size_t)n0 * 1024,
             dyn, acc);

    int t = threadIdx.x, lane = t & 31, wid = t >> 5;
    int wm = wid & 1, wn = wid >> 1;

#pragma unroll
    for (int tm = 0; tm < 4; tm++)
#pragma unroll
        for (int tn = 0; tn < 8; tn++) {
            int c  = n0 + wn * 64 + tn * 8 + (lane & 3) * 2;
            int h  = c >> 6, dk = c & 63;
#pragma unroll
            for (int half = 0; half < 2; half++) {
                int m = m0 + wm * 64 + tm * 16 + (lane >> 2) + 8 * half;
                int b = m >> 11, s = m & 2047;
                float vx = acc[tm][tn][2 * half + 0];
                float vy = acc[tm][tn][2 * half + 1];
                size_t off = ((size_t)((b * 16 + h) * 2048 + s)) * 64 + dk;
                if (z == 1) {
                    float2 v; v.x = vx; v.y = vy;
                    *(float2*)&g_Kraw[off] = v;
                } else if (z == 2) {
                    ((__half2*)g_Vh)[off >> 1] = __floats2half2_rn(vx, vy);
                } else {
                    float2 pe = *(const float2*)&g_PE[s * 64 + dk];
                    vx = (vx + pe.x) * SC2;
                    vy = (vy + pe.y) * SC2;
                    ((__half2*)g_Qh)[off >> 1] = __floats2half2_rn(vx, vy);
                }
            }
        }
}

// ---------------------------------------------------------------------------
// EMA smear on K + PE add, output fp16
// ---------------------------------------------------------------------------
__global__ void smear_kernel(const float* __restrict__ alpha) {
    int idx = blockIdx.x * blockDim.x + threadIdx.x;
    int dk = idx & 63;
    int s  = (idx >> 6) & 2047;
    int h  = (idx >> 17) & 15;
    float kc = g_Kraw[idx];
    float v;
    if (s == 0) {
        v = kc;
    } else {
        float a = 1.0f / (1.0f + expf(-alpha[h * 2047 + (s - 1)]));
        v = a * kc + (1.0f - a) * g_Kraw[idx - 64];
    }
    v += g_PE[s * 64 + dk];
    g_Kh[idx] = __float2half_rn(v);
}

// ---------------------------------------------------------------------------
// Causal flash attention, fp16 HMMA. BM=128 (8 warps, 256 thr), BN=64.
// 2-stage double-buffered KV pipeline (proven R12, unchanged).
// ---------------------------------------------------------------------------
#define ASTR 144
#define AMAT (64 * ASTR)    // 9216
#define KVSTG (2 * AMAT)    // 18432 per stage

__global__ __launch_bounds__(256, 2) void attn_mma() {
    __shared__ __align__(16) char sm[2 * KVSTG];
    uint32_t sb = smem_u32(sm);

    int t = threadIdx.x, lane = t & 31, w = t >> 5;   // w = 0..7
    int qt = 15 - (int)blockIdx.x;          // heavy tiles first
    int qb = qt * 128;
    int bh = blockIdx.y;
    size_t base = (size_t)bh * SS * DKK;

    // ---- stage Q tile, extract frags ----
    {
        const char* qsrc = (const char*)(g_Qh + base);
#pragma unroll
        for (int q = 0; q < 4; q++) {
            int idx = t * 4 + q;
            int r   = idx >> 3;
            int c   = idx & 7;
            CPA16(sb + r * ASTR + c * 16,
                  qsrc + ((size_t)(qb + r) * 64 + c * 8) * 2);
        }
        CPA_COMMIT(); CPA_WAIT0();
        __syncthreads();
    }

    uint32_t qF[4][4];
    {
        int ar = w * 16 + (lane & 15);
#pragma unroll
        for (int k = 0; k < 4; k++) {
            uint32_t acol = (uint32_t)(k * 32 + (lane >> 4) * 16);
            ldsm_x4(qF[k], sb + ar * ASTR + acol);
        }
    }
    __syncthreads();

    float o[8][4];
    float m2[2], lsum[2];
#pragma unroll
    for (int j = 0; j < 8; j++)
#pragma unroll
        for (int u = 0; u < 4; u++) o[j][u] = 0.0f;
    m2[0] = m2[1] = -1e30f;
    lsum[0] = lsum[1] = 0.0f;

    const char* kvsrc[2] = {(const char*)(g_Kh + base), (const char*)(g_Vh + base)};

    auto load_kv = [&](int tile, int st) {
        uint32_t stb = sb + st * KVSTG;
        int kb = tile * 64;
#pragma unroll
        for (int q = 0; q < 4; q++) {
            int idx = t * 4 + q;
            int mat = idx >> 9;
            int r   = (idx >> 3) & 63;
            int c   = idx & 7;
            CPA16(stb + mat * AMAT + r * ASTR + c * 16,
                  kvsrc[mat] + ((size_t)(kb + r) * 64 + c * 8) * 2);
        }
        CPA_COMMIT();
    };

    int r0 = (lane >> 2);
    int ntiles = 2 * qt + 2;

    load_kv(0, 0);
    if (ntiles > 1) load_kv(1, 1);

    for (int tile = 0; tile < ntiles; tile++) {
        int kb = tile * 64;
        int st = tile & 1;
        if (tile + 1 < ntiles) { CPA_WAIT1(); } else { CPA_WAIT0(); }
        __syncthreads();

        uint32_t stb = sb + st * KVSTG;
        bool active = (kb <= qb + w * 16 + 15);

        if (active) {
            float s[8][4];
#pragma unroll
            for (int j = 0; j < 8; j++)
#pragma unroll
                for (int u = 0; u < 4; u++) s[j][u] = 0.0f;

            {
                int b_row = (lane & 7) + 8 * (lane >> 4);
#pragma unroll
                for (int k = 0; k < 4; k++) {
                    uint32_t bcol = (uint32_t)((k * 16 + 8 * ((lane >> 3) & 1)) * 2);
                    uint32_t kF[8][2];
#pragma unroll
                    for (int tp = 0; tp < 4; tp++) {
                        uint32_t off = (uint32_t)((b_row + 16 * tp) * ASTR) + bcol;
                        ldsm_x4(&kF[2 * tp][0], stb + 0 * AMAT + off);
                    }
#pragma unroll
                    for (int j = 0; j < 8; j++) mma_f16(s[j], qF[k], kF[j]);
                }
            }

            if (kb + 63 > qb + w * 16) {
#pragma unroll
                for (int j = 0; j < 8; j++)
#pragma unroll
                    for (int u = 0; u < 4; u++) {
                        int row = qb + w * 16 + r0 + 8 * (u >> 1);
                        int col = kb + j * 8 + 2 * (lane & 3) + (u & 1);
                        if (col > row) s[j][u] = -1e30f;
                    }
            }

#pragma unroll
            for (int h = 0; h < 2; h++) {
                float mx = -1e30f;
#pragma unroll
                for (int j = 0; j < 8; j++) {
                    mx = fmaxf(mx, s[j][2 * h + 0]);
                    mx = fmaxf(mx, s[j][2 * h + 1]);
                }
                mx = fmaxf(mx, __shfl_xor_sync(0xffffffffu, mx, 1));
                mx = fmaxf(mx, __shfl_xor_sync(0xffffffffu, mx, 2));
                float mnew = fmaxf(m2[h], mx);
                float corr = ex2(m2[h] - mnew);
                m2[h] = mnew;
                float rs = 0.0f;
#pragma unroll
                for (int j = 0; j < 8; j++) {
                    float p0 = ex2(s[j][2 * h + 0] - mnew);
                    float p1 = ex2(s[j][2 * h + 1] - mnew);
                    s[j][2 * h + 0] = p0;
                    s[j][2 * h + 1] = p1;
                    rs += p0 + p1;
                }
                lsum[h] = lsum[h] * corr + rs;
#pragma unroll
                for (int j = 0; j < 8; j++) {
                    o[j][2 * h + 0] *= corr;
                    o[j][2 * h + 1] *= corr;
                }
            }

            uint32_t pF[4][4];
#pragma unroll
            for (int kk = 0; kk < 4; kk++) {
                int j = 2 * kk;
#pragma unroll
                for (int q = 0; q < 4; q++) {
                    int jj = j + (q >> 1);
                    __half2 hp = __floats2half2_rn(s[jj][(q & 1) * 2 + 0],
                                                   s[jj][(q & 1) * 2 + 1]);
                    pF[kk][q] = *(uint32_t*)&hp;
                }
            }

            {
                int vrow = (lane & 7) + 8 * ((lane >> 3) & 1);
                uint32_t vcol = (uint32_t)(16 * (lane >> 4));
#pragma unroll
                for (int kk = 0; kk < 4; kk++) {
                    uint32_t vF[8][2];
#pragma unroll
                    for (int jj = 0; jj < 4; jj++) {
                        uint32_t off = (uint32_t)((kk * 16 + vrow) * ASTR) + (uint32_t)(jj * 32) + vcol;
                        ldsm_x4_t(&vF[2 * jj][0], stb + 1 * AMAT + off);
                    }
#pragma unroll
                    for (int j = 0; j < 8; j++) mma_f16(o[j], pF[kk], vF[j]);
                }
            }
        }

        __syncthreads();
        if (tile + 2 < ntiles) load_kv(tile + 2, st);
    }

#pragma unroll
    for (int h = 0; h < 2; h++) {
        lsum[h] += __shfl_xor_sync(0xffffffffu, lsum[h], 1);
        lsum[h] += __shfl_xor_sync(0xffffffffu, lsum[h], 2);
        lsum[h] = 1.0f / lsum[h];
    }

    int b = bh >> 4, hh = bh & 15;
#pragma unroll
    for (int j = 0; j < 8; j++) {
        int dk = j * 8 + 2 * (lane & 3);
#pragma unroll
        for (int h = 0; h < 2; h++) {
            int srow = qb + w * 16 + r0 + 8 * h;
            float f0 = o[j][2 * h + 0] * lsum[h];
            float f1 = o[j][2 * h + 1] * lsum[h];
            size_t off = ((size_t)(b * SS + srow) * DD + hh * 64 + dk) >> 1;
            ((__half2*)g_Ah)[off] = __floats2half2_rn(f0, f1);
        }
    }
}

// ---------------------------------------------------------------------------
// Output projection GEMM: Y = attn @ Wo^T + X
// ---------------------------------------------------------------------------
__global__ __launch_bounds__(128, 2) void oproj_mma(const float* __restrict__ X) {
    extern __shared__ char dyn[];
    float acc[4][8][4];

    int m0 = blockIdx.y * 128;
    int n0 = blockIdx.x * 128;

    mma_gemm(g_Ah + (size_t)m0 * 1024, g_Woh + (size_t)n0 * 1024, dyn, acc);

    int t = threadIdx.x, lane = t & 31, wid = t >> 5;
    int wm = wid & 1, wn = wid >> 1;
#pragma unroll
    for (int tm = 0; tm < 4; tm++)
#pragma unroll
        for (int tn = 0; tn < 8; tn++) {
            int c = n0 + wn * 64 + tn * 8 + (lane & 3) * 2;
#pragma unroll
            for (int half = 0; half < 2; half++) {
                int m = m0 + wm * 64 + tm * 16 + (lane >> 2) + 8 * half;
                float2 xr = *(const float2*)&X[(size_t)m * 1024 + c];
                float2 v;
                v.x = acc[tm][tn][2 * half + 0] + xr.x;
                v.y = acc[tm][tn][2 * half + 1] + xr.y;
                *(float2*)&g_Y[(size_t)m * 1024 + c] = v;
            }
        }
}

// ---------------------------------------------------------------------------
// LayerNorm over D=1024 per row
// ---------------------------------------------------------------------------
__global__ void ln_kernel(const float* __restrict__ gamma,
                          const float* __restrict__ beta,
                          float* __restrict__ out)
{
    int row = blockIdx.x;
    int t   = threadIdx.x;
    const float* y = g_Y + (size_t)row * 1024;

    float x[4];
    float s = 0.0f;
#pragma unroll
    for (int u = 0; u < 4; u++) { x[u] = y[t + 256 * u]; s += x[u]; }

    __shared__ float red[32];
#pragma unroll
    for (int off = 16; off; off >>= 1) s += __shfl_xor_sync(0xffffffffu, s, off);
    if ((t & 31) == 0) red[t >> 5] = s;
    __syncthreads();
    if (t == 0) {
        float tot = 0.0f;
        for (int w = 0; w < 8; w++) tot += red[w];
        red[8] = tot;
    }
    __syncthreads();
    float mean = red[8] * (1.0f / 1024.0f);

    float vs = 0.0f;
#pragma unroll
    for (int u = 0; u < 4; u++) { float d = x[u] - mean; vs += d * d; }
#pragma unroll
    for (int off = 16; off; off >>= 1) vs += __shfl_xor_sync(0xffffffffu, vs, off);
    if ((t & 31) == 0) red[16 + (t >> 5)] = vs;
    __syncthreads();
    if (t == 0) {
        float tot = 0.0f;
        for (int w = 0; w < 8; w++) tot += red[16 + w];
        red[24] = tot;
    }
    __syncthreads();
    float var  = red[24] * (1.0f / 1024.0f);
    float rstd = rsqrtf(var + 1e-5f);

#pragma unroll
    for (int u = 0; u < 4; u++) {
        int c = t + 256 * u;
        out[(size_t)row * 1024 + c] = (x[u] - mean) * rstd * gamma[c] + beta[c];
    }
}

// ---------------------------------------------------------------------------
extern "C" void kernel_launch(void* const* d_in, const int* in_sizes, int n_in,
                              void* d_out, int out_size)
{
    const float* X     = (const float*)d_in[0];
    const float* Wq    = (const float*)d_in[1];
    const float* Wk    = (const float*)d_in[2];
    const float* Wv    = (const float*)d_in[3];
    const float* Wo    = (const float*)d_in[4];
    const float* alpha = (const float*)d_in[5];
    const float* lns   = (const float*)d_in[6];
    const float* lnb   = (const float*)d_in[7];
    float* out = (float*)d_out;

    static int attr_set = 0;
    if (!attr_set) {
        cudaFuncSetAttribute(qkv_mma,   cudaFuncAttributeMaxDynamicSharedMemorySize, DYN_SMEM);
        cudaFuncSetAttribute(oproj_mma, cudaFuncAttributeMaxDynamicSharedMemorySize, DYN_SMEM);
        attr_set = 1;
    }

    prep_kernel<<<8704, 256>>>(X, Wq, Wk, Wv, Wo);                 // 1
    qkv_mma<<<dim3(8, 32, 3), 128, DYN_SMEM>>>();                  // 2
    smear_kernel<<<(MM * DD) / 256, 256>>>(alpha);                 // 3
    attn_mma<<<dim3(16, 32), 256>>>();                             // 4
    oproj_mma<<<dim3(8, 32), 128, DYN_SMEM>>>(X);                  // 5
    ln_kernel<<<MM, 256>>>(lns, lnb, out);                         // 6
}

// round 15
// speedup vs baseline: 1.0893x; 1.0049x over previous
#include <cuda_runtime.h>
#include <cuda_fp16.h>
#include <math.h>
#include <stdint.h>

#define BB  2
#define SS  2048
#define DD  1024
#define HH  16
#define DKK 64
#define MM  (BB*SS)   // 4096 rows

// scale folded into Q: 1/sqrt(64) * log2(e)
#define SC2 0.18033688011112042f

// ---------------------------------------------------------------------------
// Scratch (allocation-free rule: __device__ globals)
// ---------------------------------------------------------------------------
__device__ __align__(16) float g_PE[SS*DKK];
__device__ __align__(16) float g_Kraw[MM*DD];
__device__ __align__(16) float g_Y[MM*DD];

__device__ __align__(16) __half g_Xh[MM*DD];
__device__ __align__(16) __half g_Wh[3*DD*DD];
__device__ __align__(16) __half g_Woh[DD*DD];
__device__ __align__(16) __half g_Ah[MM*DD];

// attention operands, head-split [B*H][S][64]
__device__ __align__(16) __half g_Qh[MM*DD];
__device__ __align__(16) __half g_Kh[MM*DD];
__device__ __align__(16) __half g_Vh[MM*DD];

// ---------------------------------------------------------------------------
// PTX helpers (baseline sm_103-safe)
// ---------------------------------------------------------------------------
__device__ __forceinline__ uint32_t smem_u32(const void* p) {
    uint32_t a;
    asm("{ .reg .u64 t; cvta.to.shared.u64 t, %1; cvt.u32.u64 %0, t; }"
        : "=r"(a) : "l"(p));
    return a;
}

#define CPA16(dst, src) \
    asm volatile("cp.async.cg.shared.global [%0], [%1], 16;" :: "r"(dst), "l"(src) : "memory")
#define CPA_COMMIT() asm volatile("cp.async.commit_group;" ::: "memory")
#define CPA_WAIT1()  asm volatile("cp.async.wait_group 1;" ::: "memory")
#define CPA_WAIT0()  asm volatile("cp.async.wait_group 0;" ::: "memory")

__device__ __forceinline__ void ldsm_x4(uint32_t* r, uint32_t addr) {
    asm volatile("ldmatrix.sync.aligned.m8n8.x4.shared.b16 {%0,%1,%2,%3}, [%4];"
                 : "=r"(r[0]), "=r"(r[1]), "=r"(r[2]), "=r"(r[3]) : "r"(addr));
}
__device__ __forceinline__ void ldsm_x4_t(uint32_t* r, uint32_t addr) {
    asm volatile("ldmatrix.sync.aligned.m8n8.x4.trans.shared.b16 {%0,%1,%2,%3}, [%4];"
                 : "=r"(r[0]), "=r"(r[1]), "=r"(r[2]), "=r"(r[3]) : "r"(addr));
}

__device__ __forceinline__ void mma_f16(float* c, const uint32_t* a, const uint32_t* b) {
    asm volatile(
        "mma.sync.aligned.m16n8k16.row.col.f32.f16.f16.f32 "
        "{%0,%1,%2,%3}, {%4,%5,%6,%7}, {%8,%9}, {%0,%1,%2,%3};"
        : "+f"(c[0]), "+f"(c[1]), "+f"(c[2]), "+f"(c[3])
        : "r"(a[0]), "r"(a[1]), "r"(a[2]), "r"(a[3]), "r"(b[0]), "r"(b[1]));
}

__device__ __forceinline__ float ex2(float x) {
    float r;
    asm("ex2.approx.ftz.f32 %0, %1;" : "=f"(r) : "f"(x));
    return r;
}

// ---------------------------------------------------------------------------
// prep: convx (blocks 0..4095) + convw (4096..8191) + pe (8192..8703)
// ---------------------------------------------------------------------------
__global__ void prep_kernel(const float* __restrict__ X,
                            const float* __restrict__ Wq, const float* __restrict__ Wk,
                            const float* __restrict__ Wv, const float* __restrict__ Wo) {
    int bid = blockIdx.x;
    int t   = threadIdx.x;
    if (bid < 4096) {
        int i = bid * 256 + t;
        float4 v = ((const float4*)X)[i];
        __half2* hp = (__half2*)g_Xh;
        hp[2*i]   = __floats2half2_rn(v.x, v.y);
        hp[2*i+1] = __floats2half2_rn(v.z, v.w);
    } else if (bid < 8192) {
        int gi  = (bid - 4096) * 256 + t;
        int mat = gi >> 18;
        int i   = gi & 0x3FFFF;
        const float* src = (mat == 0) ? Wq : (mat == 1) ? Wk : (mat == 2) ? Wv : Wo;
        __half2* hp = (mat < 3) ? (__half2*)(g_Wh + (size_t)mat * DD * DD)
                                : (__half2*)g_Woh;
        float4 v = ((const float4*)src)[i];
        hp[2*i]   = __floats2half2_rn(v.x, v.y);
        hp[2*i+1] = __floats2half2_rn(v.z, v.w);
    } else {
        int idx = (bid - 8192) * 256 + t;
        int s  = idx >> 6;
        int dk = idx & 63;
        int i  = dk >> 1;
        float freq = expf(-((float)(2 * i) / 64.0f) * 9.210340371976184f);
        float ang  = (float)s * freq;
        g_PE[idx]  = (dk & 1) ? cosf(ang) : sinf(ang);
    }
}

// ---------------------------------------------------------------------------
// fp16 single-pass HMMA GEMM (proven R11/R12 config, frozen)
// ---------------------------------------------------------------------------
#define MATB 8192            // 128 * 64
#define STG  (2 * MATB)      // 16384
#define DYN_SMEM (3 * STG)   // 49152

__device__ __forceinline__ void mma_gemm(
    const __half* __restrict__ A, const __half* __restrict__ B,
    char* dyn, float acc[4][8][4])
{
    int t    = threadIdx.x;
    int lane = t & 31;
    int wid  = t >> 5;
    int wm   = wid & 1;
    int wn   = wid >> 1;
    uint32_t sbase = smem_u32(dyn);

    const char* mats[2] = {(const char*)A, (const char*)B};

#pragma unroll
    for (int tm = 0; tm < 4; tm++)
#pragma unroll
        for (int tn = 0; tn < 8; tn++)
#pragma unroll
            for (int u = 0; u < 4; u++) acc[tm][tn][u] = 0.0f;

    int idx0 = t * 8;
    auto load_stage = [&](int st, int kb) {
        uint32_t stb = sbase + st * STG;
#pragma unroll
        for (int q = 0; q < 8; q++) {
            int idx = idx0 + q;
            int mat = idx >> 9;
            int r   = (idx >> 2) & 127;
            int c   = idx & 3;
            uint32_t dst = stb + mat * MATB + r * 64 + ((c ^ ((r >> 1) & 3)) << 4);
            const char* src = mats[mat] + ((size_t)r * 1024 + kb + c * 8) * 2;
            CPA16(dst, src);
        }
        CPA_COMMIT();
    };

    int a_hi = lane >> 4;
    int b_hi = (lane >> 3) & 1;
    uint32_t aOff[4]; int aMsk[4];
#pragma unroll
    for (int tm = 0; tm < 4; tm++) {
        int r = wm * 64 + (lane & 15) + 16 * tm;
        aOff[tm] = (uint32_t)(r * 64);
        aMsk[tm] = (r >> 1) & 3;
    }
    uint32_t bOff[4]; int bMsk[4];
#pragma unroll
    for (int tp = 0; tp < 4; tp++) {
        int r = wn * 64 + (lane & 7) + 8 * (lane >> 4) + 16 * tp;
        bOff[tp] = (uint32_t)(r * 64);
        bMsk[tp] = (r >> 1) & 3;
    }

    load_stage(0, 0);
    load_stage(1, 32);

    int st = 0;
    for (int it = 0; it < 32; it++) {
        if (it < 31) { CPA_WAIT1(); } else { CPA_WAIT0(); }
        __syncthreads();
        if (it + 2 < 32) {
            int s2 = st + 2; if (s2 >= 3) s2 -= 3;
            load_stage(s2, (it + 2) * 32);
        }

        uint32_t stb = sbase + st * STG;
#pragma unroll
        for (int ks = 0; ks < 2; ks++) {
            int cA = 2 * ks + a_hi;
            int cB = 2 * ks + b_hi;
            uint32_t aF[4][4], bF[8][2];
#pragma unroll
            for (int tm = 0; tm < 4; tm++) {
                uint32_t off = aOff[tm] + (uint32_t)((cA ^ aMsk[tm]) << 4);
                ldsm_x4(aF[tm], stb + 0 * MATB + off);
            }
#pragma unroll
            for (int tp = 0; tp < 4; tp++) {
                uint32_t off = bOff[tp] + (uint32_t)((cB ^ bMsk[tp]) << 4);
                ldsm_x4(&bF[2 * tp][0], stb + 1 * MATB + off);
            }
#pragma unroll
            for (int tm = 0; tm < 4; tm++)
#pragma unroll
                for (int tn = 0; tn < 8; tn++)
                    mma_f16(acc[tm][tn], aF[tm], bF[tn]);
        }
        st++; if (st == 3) st = 0;
    }
    __syncthreads();
}

// ---------------------------------------------------------------------------
// QKV GEMM. z=0: Q -> (acc+PE)*SC2 fp16; z=1: K fp32; z=2: V fp16
// ---------------------------------------------------------------------------
__global__ __launch_bounds__(128, 2) void qkv_mma() {
    extern __shared__ char dyn[];
    float acc[4][8][4];

    int z  = blockIdx.z;
    int m0 = blockIdx.y * 128;
    int n0 = blockIdx.x * 128;

    mma_gemm(g_Xh + (size_t)m0 * 1024,
             g_Wh + (size_t)z * DD * DD + (size_t)n0 * 1024,
             dyn, acc);

    int t = threadIdx.x, lane = t & 31, wid = t >> 5;
    int wm = wid & 1, wn = wid >> 1;

#pragma unroll
    for (int tm = 0; tm < 4; tm++)
#pragma unroll
        for (int tn = 0; tn < 8; tn++) {
            int c  = n0 + wn * 64 + tn * 8 + (lane & 3) * 2;
            int h  = c >> 6, dk = c & 63;
#pragma unroll
            for (int half = 0; half < 2; half++) {
                int m = m0 + wm * 64 + tm * 16 + (lane >> 2) + 8 * half;
                int b = m >> 11, s = m & 2047;
                float vx = acc[tm][tn][2 * half + 0];
                float vy = acc[tm][tn][2 * half + 1];
                size_t off = ((size_t)((b * 16 + h) * 2048 + s)) * 64 + dk;
                if (z == 1) {
                    float2 v; v.x = vx; v.y = vy;
                    *(float2*)&g_Kraw[off] = v;
                } else if (z == 2) {
                    ((__half2*)g_Vh)[off >> 1] = __floats2half2_rn(vx, vy);
                } else {
                    float2 pe = *(const float2*)&g_PE[s * 64 + dk];
                    vx = (vx + pe.x) * SC2;
                    vy = (vy + pe.y) * SC2;
                    ((__half2*)g_Qh)[off >> 1] = __floats2half2_rn(vx, vy);
                }
            }
        }
}

// ---------------------------------------------------------------------------
// EMA smear on K + PE add, output fp16
// ---------------------------------------------------------------------------
__global__ void smear_kernel(const float* __restrict__ alpha) {
    int idx = blockIdx.x * blockDim.x + threadIdx.x;
    int dk = idx & 63;
    int s  = (idx >> 6) & 2047;
    int h  = (idx >> 17) & 15;
    float kc = g_Kraw[idx];
    float v;
    if (s == 0) {
        v = kc;
    } else {
        float a = 1.0f / (1.0f + expf(-alpha[h * 2047 + (s - 1)]));
        v = a * kc + (1.0f - a) * g_Kraw[idx - 64];
    }
    v += g_PE[s * 64 + dk];
    g_Kh[idx] = __float2half_rn(v);
}

// ---------------------------------------------------------------------------
// Causal flash attention, fp16 HMMA. BM=128 (8 warps, 256 thr), BN=64.
// 3-stage KV ring, ONE __syncthreads per tile (GEMM-proven structure).
// Dynamic smem: 3 stages x (K,V) = 55296 B.
// ---------------------------------------------------------------------------
#define ASTR 144
#define AMAT (64 * ASTR)    // 9216
#define KVSTG (2 * AMAT)    // 18432 per stage
#define ATT_SMEM (3 * KVSTG) // 55296

__global__ __launch_bounds__(256, 2) void attn_mma() {
    extern __shared__ __align__(16) char asm_dyn[];
    uint32_t sb = smem_u32(asm_dyn);

    int t = threadIdx.x, lane = t & 31, w = t >> 5;   // w = 0..7
    int qt = 15 - (int)blockIdx.x;          // heavy tiles first
    int qb = qt * 128;
    int bh = blockIdx.y;
    size_t base = (size_t)bh * SS * DKK;

    // ---- stage Q tile into stage-0 region, extract frags ----
    {
        const char* qsrc = (const char*)(g_Qh + base);
#pragma unroll
        for (int q = 0; q < 4; q++) {
            int idx = t * 4 + q;
            int r   = idx >> 3;
            int c   = idx & 7;
            CPA16(sb + r * ASTR + c * 16,
                  qsrc + ((size_t)(qb + r) * 64 + c * 8) * 2);
        }
        CPA_COMMIT(); CPA_WAIT0();
        __syncthreads();
    }

    uint32_t qF[4][4];
    {
        int ar = w * 16 + (lane & 15);
#pragma unroll
        for (int k = 0; k < 4; k++) {
            uint32_t acol = (uint32_t)(k * 32 + (lane >> 4) * 16);
            ldsm_x4(qF[k], sb + ar * ASTR + acol);
        }
    }
    __syncthreads();   // Q frags extracted before stage 0 reused for KV

    float o[8][4];
    float m2[2], lsum[2];
#pragma unroll
    for (int j = 0; j < 8; j++)
#pragma unroll
        for (int u = 0; u < 4; u++) o[j][u] = 0.0f;
    m2[0] = m2[1] = -1e30f;
    lsum[0] = lsum[1] = 0.0f;

    const char* kvsrc[2] = {(const char*)(g_Kh + base), (const char*)(g_Vh + base)};

    auto load_kv = [&](int tile, int st) {
        uint32_t stb = sb + st * KVSTG;
        int kb = tile * 64;
#pragma unroll
        for (int q = 0; q < 4; q++) {
            int idx = t * 4 + q;
            int mat = idx >> 9;
            int r   = (idx >> 3) & 63;
            int c   = idx & 7;
            CPA16(stb + mat * AMAT + r * ASTR + c * 16,
                  kvsrc[mat] + ((size_t)(kb + r) * 64 + c * 8) * 2);
        }
        CPA_COMMIT();
    };

    int r0 = (lane >> 2);
    int ntiles = 2 * qt + 2;

    load_kv(0, 0);
    if (ntiles > 1) load_kv(1, 1);

    int st = 0;
    for (int tile = 0; tile < ntiles; tile++) {
        int kb = tile * 64;
        if (tile + 1 < ntiles) { CPA_WAIT1(); } else { CPA_WAIT0(); }
        __syncthreads();           // tile data ready AND all warps done with stage of tile-1
        if (tile + 2 < ntiles) {
            int s2 = st + 2; if (s2 >= 3) s2 -= 3;   // stage of tile-1 (free now)
            load_kv(tile + 2, s2);
        }

        uint32_t stb = sb + st * KVSTG;
        bool active = (kb <= qb + w * 16 + 15);   // skip fully-masked tiles

        if (active) {
            // ---- S = Q K^T ----
            float s[8][4];
#pragma unroll
            for (int j = 0; j < 8; j++)
#pragma unroll
                for (int u = 0; u < 4; u++) s[j][u] = 0.0f;

            {
                int b_row = (lane & 7) + 8 * (lane >> 4);
#pragma unroll
                for (int k = 0; k < 4; k++) {
                    uint32_t bcol = (uint32_t)((k * 16 + 8 * ((lane >> 3) & 1)) * 2);
                    uint32_t kF[8][2];
#pragma unroll
                    for (int tp = 0; tp < 4; tp++) {
                        uint32_t off = (uint32_t)((b_row + 16 * tp) * ASTR) + bcol;
                        ldsm_x4(&kF[2 * tp][0], stb + 0 * AMAT + off);
                    }
#pragma unroll
                    for (int j = 0; j < 8; j++) mma_f16(s[j], qF[k], kF[j]);
                }
            }

            // ---- mask (global row/col) ----
            if (kb + 63 > qb + w * 16) {
#pragma unroll
                for (int j = 0; j < 8; j++)
#pragma unroll
                    for (int u = 0; u < 4; u++) {
                        int row = qb + w * 16 + r0 + 8 * (u >> 1);
                        int col = kb + j * 8 + 2 * (lane & 3) + (u & 1);
                        if (col > row) s[j][u] = -1e30f;
                    }
            }

            // ---- online softmax (base 2), per row half ----
#pragma unroll
            for (int h = 0; h < 2; h++) {
                float mx = -1e30f;
#pragma unroll
                for (int j = 0; j < 8; j++) {
                    mx = fmaxf(mx, s[j][2 * h + 0]);
                    mx = fmaxf(mx, s[j][2 * h + 1]);
                }
                mx = fmaxf(mx, __shfl_xor_sync(0xffffffffu, mx, 1));
                mx = fmaxf(mx, __shfl_xor_sync(0xffffffffu, mx, 2));
                float mnew = fmaxf(m2[h], mx);
                float corr = ex2(m2[h] - mnew);
                m2[h] = mnew;
                float rs = 0.0f;
#pragma unroll
                for (int j = 0; j < 8; j++) {
                    float p0 = ex2(s[j][2 * h + 0] - mnew);
                    float p1 = ex2(s[j][2 * h + 1] - mnew);
                    s[j][2 * h + 0] = p0;
                    s[j][2 * h + 1] = p1;
                    rs += p0 + p1;
                }
                lsum[h] = lsum[h] * corr + rs;
#pragma unroll
                for (int j = 0; j < 8; j++) {
                    o[j][2 * h + 0] *= corr;
                    o[j][2 * h + 1] *= corr;
                }
            }

            // ---- P fragments (C->A remap, fp16) ----
            uint32_t pF[4][4];
#pragma unroll
            for (int kk = 0; kk < 4; kk++) {
                int j = 2 * kk;
#pragma unroll
                for (int q = 0; q < 4; q++) {
                    int jj = j + (q >> 1);
                    __half2 hp = __floats2half2_rn(s[jj][(q & 1) * 2 + 0],
                                                   s[jj][(q & 1) * 2 + 1]);
                    pF[kk][q] = *(uint32_t*)&hp;
                }
            }

            // ---- O += P V, V via ldmatrix.trans (mat 1) ----
            {
                int vrow = (lane & 7) + 8 * ((lane >> 3) & 1);
                uint32_t vcol = (uint32_t)(16 * (lane >> 4));
#pragma unroll
                for (int kk = 0; kk < 4; kk++) {
                    uint32_t vF[8][2];
#pragma unroll
                    for (int jj = 0; jj < 4; jj++) {
                        uint32_t off = (uint32_t)((kk * 16 + vrow) * ASTR) + (uint32_t)(jj * 32) + vcol;
                        ldsm_x4_t(&vF[2 * jj][0], stb + 1 * AMAT + off);
                    }
#pragma unroll
                    for (int j = 0; j < 8; j++) mma_f16(o[j], pF[kk], vF[j]);
                }
            }
        }

        st++; if (st == 3) st = 0;
    }

    // ---- epilogue: normalize, fp16, store ----
#pragma unroll
    for (int h = 0; h < 2; h++) {
        lsum[h] += __shfl_xor_sync(0xffffffffu, lsum[h], 1);
        lsum[h] += __shfl_xor_sync(0xffffffffu, lsum[h], 2);
        lsum[h] = 1.0f / lsum[h];
    }

    int b = bh >> 4, hh = bh & 15;
#pragma unroll
    for (int j = 0; j < 8; j++) {
        int dk = j * 8 + 2 * (lane & 3);
#pragma unroll
        for (int h = 0; h < 2; h++) {
            int srow = qb + w * 16 + r0 + 8 * h;
            float f0 = o[j][2 * h + 0] * lsum[h];
            float f1 = o[j][2 * h + 1] * lsum[h];
            size_t off = ((size_t)(b * SS + srow) * DD + hh * 64 + dk) >> 1;
            ((__half2*)g_Ah)[off] = __floats2half2_rn(f0, f1);
        }
    }
}

// ---------------------------------------------------------------------------
// Output projection GEMM: Y = attn @ Wo^T + X
// ---------------------------------------------------------------------------
__global__ __launch_bounds__(128, 2) void oproj_mma(const float* __restrict__ X) {
    extern __shared__ char dyn[];
    float acc[4][8][4];

    int m0 = blockIdx.y * 128;
    int n0 = blockIdx.x * 128;

    mma_gemm(g_Ah + (size_t)m0 * 1024, g_Woh + (size_t)n0 * 1024, dyn, acc);

    int t = threadIdx.x, lane = t & 31, wid = t >> 5;
    int wm = wid & 1, wn = wid >> 1;
#pragma unroll
    for (int tm = 0; tm < 4; tm++)
#pragma unroll
        for (int tn = 0; tn < 8; tn++) {
            int c = n0 + wn * 64 + tn * 8 + (lane & 3) * 2;
#pragma unroll
            for (int half = 0; half < 2; half++) {
                int m = m0 + wm * 64 + tm * 16 + (lane >> 2) + 8 * half;
                float2 xr = *(const float2*)&X[(size_t)m * 1024 + c];
                float2 v;
                v.x = acc[tm][tn][2 * half + 0] + xr.x;
                v.y = acc[tm][tn][2 * half + 1] + xr.y;
                *(float2*)&g_Y[(size_t)m * 1024 + c] = v;
            }
        }
}

// ---------------------------------------------------------------------------
// LayerNorm over D=1024 per row
// ---------------------------------------------------------------------------
__global__ void ln_kernel(const float* __restrict__ gamma,
                          const float* __restrict__ beta,
                          float* __restrict__ out)
{
    int row = blockIdx.x;
    int t   = threadIdx.x;
    const float* y = g_Y + (size_t)row * 1024;

    float x[4];
    float s = 0.0f;
#pragma unroll
    for (int u = 0; u < 4; u++) { x[u] = y[t + 256 * u]; s += x[u]; }

    __shared__ float red[32];
#pragma unroll
    for (int off = 16; off; off >>= 1) s += __shfl_xor_sync(0xffffffffu, s, off);
    if ((t & 31) == 0) red[t >> 5] = s;
    __syncthreads();
    if (t == 0) {
        float tot = 0.0f;
        for (int w = 0; w < 8; w++) tot += red[w];
        red[8] = tot;
    }
    __syncthreads();
    float mean = red[8] * (1.0f / 1024.0f);

    float vs = 0.0f;
#pragma unroll
    for (int u = 0; u < 4; u++) { float d = x[u] - mean; vs += d * d; }
#pragma unroll
    for (int off = 16; off; off >>= 1) vs += __shfl_xor_sync(0xffffffffu, vs, off);
    if ((t & 31) == 0) red[16 + (t >> 5)] = vs;
    __syncthreads();
    if (t == 0) {
        float tot = 0.0f;
        for (int w = 0; w < 8; w++) tot += red[16 + w];
        red[24] = tot;
    }
    __syncthreads();
    float var  = red[24] * (1.0f / 1024.0f);
    float rstd = rsqrtf(var + 1e-5f);

#pragma unroll
    for (int u = 0; u < 4; u++) {
        int c = t + 256 * u;
        out[(size_t)row * 1024 + c] = (x[u] - mean) * rstd * gamma[c] + beta[c];
    }
}

// ---------------------------------------------------------------------------
extern "C" void kernel_launch(void* const* d_in, const int* in_sizes, int n_in,
                              void* d_out, int out_size)
{
    const float* X     = (const float*)d_in[0];
    const float* Wq    = (const float*)d_in[1];
    const float* Wk    = (const float*)d_in[2];
    const float* Wv    = (const float*)d_in[3];
    const float* Wo    = (const float*)d_in[4];
    const float* alpha = (const float*)d_in[5];
    const float* lns   = (const float*)d_in[6];
    const float* lnb   = (const float*)d_in[7];
    float* out = (float*)d_out;

    static int attr_set = 0;
    if (!attr_set) {
        cudaFuncSetAttribute(qkv_mma,   cudaFuncAttributeMaxDynamicSharedMemorySize, DYN_SMEM);
        cudaFuncSetAttribute(oproj_mma, cudaFuncAttributeMaxDynamicSharedMemorySize, DYN_SMEM);
        cudaFuncSetAttribute(attn_mma,  cudaFuncAttributeMaxDynamicSharedMemorySize, ATT_SMEM);
        attr_set = 1;
    }

    prep_kernel<<<8704, 256>>>(X, Wq, Wk, Wv, Wo);                 // 1
    qkv_mma<<<dim3(8, 32, 3), 128, DYN_SMEM>>>();                  // 2
    smear_kernel<<<(MM * DD) / 256, 256>>>(alpha);                 // 3
    attn_mma<<<dim3(16, 32), 256, ATT_SMEM>>>();                   // 4
    oproj_mma<<<dim3(8, 32), 128, DYN_SMEM>>>(X);                  // 5
    ln_kernel<<<MM, 256>>>(lns, lnb, out);                         // 6
}

// round 16
// speedup vs baseline: 1.2088x; 1.1097x over previous
#include <cuda_runtime.h>
#include <cuda_fp16.h>
#include <math.h>
#include <stdint.h>

#define BB  2
#define SS  2048
#define DD  1024
#define HH  16
#define DKK 64
#define MM  (BB*SS)   // 4096 rows

// scale folded into Q: 1/sqrt(64) * log2(e)
#define SC2 0.18033688011112042f

// ---------------------------------------------------------------------------
// Scratch (allocation-free rule: __device__ globals)
// ---------------------------------------------------------------------------
__device__ __align__(16) float g_PE[SS*DKK];
__device__ __align__(16) float g_Kraw[MM*DD];
__device__ __align__(16) float g_Y[MM*DD];

__device__ __align__(16) __half g_Xh[MM*DD];
__device__ __align__(16) __half g_Wh[3*DD*DD];
__device__ __align__(16) __half g_Woh[DD*DD];
__device__ __align__(16) __half g_Ah[MM*DD];

// attention operands, head-split [B*H][S][64]
__device__ __align__(16) __half g_Qh[MM*DD];
__device__ __align__(16) __half g_Kh[MM*DD];
__device__ __align__(16) __half g_Vh[MM*DD];

// ---------------------------------------------------------------------------
// PTX helpers (baseline sm_103-safe)
// ---------------------------------------------------------------------------
__device__ __forceinline__ uint32_t smem_u32(const void* p) {
    uint32_t a;
    asm("{ .reg .u64 t; cvta.to.shared.u64 t, %1; cvt.u32.u64 %0, t; }"
        : "=r"(a) : "l"(p));
    return a;
}

#define CPA16(dst, src) \
    asm volatile("cp.async.cg.shared.global [%0], [%1], 16;" :: "r"(dst), "l"(src) : "memory")
#define CPA_COMMIT() asm volatile("cp.async.commit_group;" ::: "memory")
#define CPA_WAIT1()  asm volatile("cp.async.wait_group 1;" ::: "memory")
#define CPA_WAIT0()  asm volatile("cp.async.wait_group 0;" ::: "memory")

__device__ __forceinline__ void ldsm_x4(uint32_t* r, uint32_t addr) {
    asm volatile("ldmatrix.sync.aligned.m8n8.x4.shared.b16 {%0,%1,%2,%3}, [%4];"
                 : "=r"(r[0]), "=r"(r[1]), "=r"(r[2]), "=r"(r[3]) : "r"(addr));
}
__device__ __forceinline__ void ldsm_x4_t(uint32_t* r, uint32_t addr) {
    asm volatile("ldmatrix.sync.aligned.m8n8.x4.trans.shared.b16 {%0,%1,%2,%3}, [%4];"
                 : "=r"(r[0]), "=r"(r[1]), "=r"(r[2]), "=r"(r[3]) : "r"(addr));
}

__device__ __forceinline__ void mma_f16(float* c, const uint32_t* a, const uint32_t* b) {
    asm volatile(
        "mma.sync.aligned.m16n8k16.row.col.f32.f16.f16.f32 "
        "{%0,%1,%2,%3}, {%4,%5,%6,%7}, {%8,%9}, {%0,%1,%2,%3};"
        : "+f"(c[0]), "+f"(c[1]), "+f"(c[2]), "+f"(c[3])
        : "r"(a[0]), "r"(a[1]), "r"(a[2]), "r"(a[3]), "r"(b[0]), "r"(b[1]));
}

__device__ __forceinline__ float ex2(float x) {
    float r;
    asm("ex2.approx.ftz.f32 %0, %1;" : "=f"(r) : "f"(x));
    return r;
}

// ---------------------------------------------------------------------------
// prep: convx (blocks 0..4095) + convw (4096..8191) + pe (8192..8703)
// ---------------------------------------------------------------------------
__global__ void prep_kernel(const float* __restrict__ X,
                            const float* __restrict__ Wq, const float* __restrict__ Wk,
                            const float* __restrict__ Wv, const float* __restrict__ Wo) {
    int bid = blockIdx.x;
    int t   = threadIdx.x;
    if (bid < 4096) {
        int i = bid * 256 + t;
        float4 v = ((const float4*)X)[i];
        __half2* hp = (__half2*)g_Xh;
        hp[2*i]   = __floats2half2_rn(v.x, v.y);
        hp[2*i+1] = __floats2half2_rn(v.z, v.w);
    } else if (bid < 8192) {
        int gi  = (bid - 4096) * 256 + t;
        int mat = gi >> 18;
        int i   = gi & 0x3FFFF;
        const float* src = (mat == 0) ? Wq : (mat == 1) ? Wk : (mat == 2) ? Wv : Wo;
        __half2* hp = (mat < 3) ? (__half2*)(g_Wh + (size_t)mat * DD * DD)
                                : (__half2*)g_Woh;
        float4 v = ((const float4*)src)[i];
        hp[2*i]   = __floats2half2_rn(v.x, v.y);
        hp[2*i+1] = __floats2half2_rn(v.z, v.w);
    } else {
        int idx = (bid - 8192) * 256 + t;
        int s  = idx >> 6;
        int dk = idx & 63;
        int i  = dk >> 1;
        float freq = expf(-((float)(2 * i) / 64.0f) * 9.210340371976184f);
        float ang  = (float)s * freq;
        g_PE[idx]  = (dk & 1) ? cosf(ang) : sinf(ang);
    }
}

// ---------------------------------------------------------------------------
// fp16 single-pass HMMA GEMM (proven R11/R12 config, frozen)
// ---------------------------------------------------------------------------
#define MATB 8192            // 128 * 64
#define STG  (2 * MATB)      // 16384
#define DYN_SMEM (3 * STG)   // 49152

__device__ __forceinline__ void mma_gemm(
    const __half* __restrict__ A, const __half* __restrict__ B,
    char* dyn, float acc[4][8][4])
{
    int t    = threadIdx.x;
    int lane = t & 31;
    int wid  = t >> 5;
    int wm   = wid & 1;
    int wn   = wid >> 1;
    uint32_t sbase = smem_u32(dyn);

    const char* mats[2] = {(const char*)A, (const char*)B};

#pragma unroll
    for (int tm = 0; tm < 4; tm++)
#pragma unroll
        for (int tn = 0; tn < 8; tn++)
#pragma unroll
            for (int u = 0; u < 4; u++) acc[tm][tn][u] = 0.0f;

    int idx0 = t * 8;
    auto load_stage = [&](int st, int kb) {
        uint32_t stb = sbase + st * STG;
#pragma unroll
        for (int q = 0; q < 8; q++) {
            int idx = idx0 + q;
            int mat = idx >> 9;
            int r   = (idx >> 2) & 127;
            int c   = idx & 3;
            uint32_t dst = stb + mat * MATB + r * 64 + ((c ^ ((r >> 1) & 3)) << 4);
            const char* src = mats[mat] + ((size_t)r * 1024 + kb + c * 8) * 2;
            CPA16(dst, src);
        }
        CPA_COMMIT();
    };

    int a_hi = lane >> 4;
    int b_hi = (lane >> 3) & 1;
    uint32_t aOff[4]; int aMsk[4];
#pragma unroll
    for (int tm = 0; tm < 4; tm++) {
        int r = wm * 64 + (lane & 15) + 16 * tm;
        aOff[tm] = (uint32_t)(r * 64);
        aMsk[tm] = (r >> 1) & 3;
    }
    uint32_t bOff[4]; int bMsk[4];
#pragma unroll
    for (int tp = 0; tp < 4; tp++) {
        int r = wn * 64 + (lane & 7) + 8 * (lane >> 4) + 16 * tp;
        bOff[tp] = (uint32_t)(r * 64);
        bMsk[tp] = (r >> 1) & 3;
    }

    load_stage(0, 0);
    load_stage(1, 32);

    int st = 0;
    for (int it = 0; it < 32; it++) {
        if (it < 31) { CPA_WAIT1(); } else { CPA_WAIT0(); }
        __syncthreads();
        if (it + 2 < 32) {
            int s2 = st + 2; if (s2 >= 3) s2 -= 3;
            load_stage(s2, (it + 2) * 32);
        }

        uint32_t stb = sbase + st * STG;
#pragma unroll
        for (int ks = 0; ks < 2; ks++) {
            int cA = 2 * ks + a_hi;
            int cB = 2 * ks + b_hi;
            uint32_t aF[4][4], bF[8][2];
#pragma unroll
            for (int tm = 0; tm < 4; tm++) {
                uint32_t off = aOff[tm] + (uint32_t)((cA ^ aMsk[tm]) << 4);
                ldsm_x4(aF[tm], stb + 0 * MATB + off);
            }
#pragma unroll
            for (int tp = 0; tp < 4; tp++) {
                uint32_t off = bOff[tp] + (uint32_t)((cB ^ bMsk[tp]) << 4);
                ldsm_x4(&bF[2 * tp][0], stb + 1 * MATB + off);
            }
#pragma unroll
            for (int tm = 0; tm < 4; tm++)
#pragma unroll
                for (int tn = 0; tn < 8; tn++)
                    mma_f16(acc[tm][tn], aF[tm], bF[tn]);
        }
        st++; if (st == 3) st = 0;
    }
    __syncthreads();
}

// ---------------------------------------------------------------------------
// QKV GEMM. z=0: Q -> (acc+PE)*SC2 fp16; z=1: K fp32; z=2: V fp16
// ---------------------------------------------------------------------------
__global__ __launch_bounds__(128, 2) void qkv_mma() {
    extern __shared__ char dyn[];
    float acc[4][8][4];

    int z  = blockIdx.z;
    int m0 = blockIdx.y * 128;
    int n0 = blockIdx.x * 128;

    mma_gemm(g_Xh + (size_t)m0 * 1024,
             g_Wh + (size_t)z * DD * DD + (size_t)n0 * 1024,
             dyn, acc);

    int t = threadIdx.x, lane = t & 31, wid = t >> 5;
    int wm = wid & 1, wn = wid >> 1;

#pragma unroll
    for (int tm = 0; tm < 4; tm++)
#pragma unroll
        for (int tn = 0; tn < 8; tn++) {
            int c  = n0 + wn * 64 + tn * 8 + (lane & 3) * 2;
            int h  = c >> 6, dk = c & 63;
#pragma unroll
            for (int half = 0; half < 2; half++) {
                int m = m0 + wm * 64 + tm * 16 + (lane >> 2) + 8 * half;
                int b = m >> 11, s = m & 2047;
                float vx = acc[tm][tn][2 * half + 0];
                float vy = acc[tm][tn][2 * half + 1];
                size_t off = ((size_t)((b * 16 + h) * 2048 + s)) * 64 + dk;
                if (z == 1) {
                    float2 v; v.x = vx; v.y = vy;
                    *(float2*)&g_Kraw[off] = v;
                } else if (z == 2) {
                    ((__half2*)g_Vh)[off >> 1] = __floats2half2_rn(vx, vy);
                } else {
                    float2 pe = *(const float2*)&g_PE[s * 64 + dk];
                    vx = (vx + pe.x) * SC2;
                    vy = (vy + pe.y) * SC2;
                    ((__half2*)g_Qh)[off >> 1] = __floats2half2_rn(vx, vy);
                }
            }
        }
}

// ---------------------------------------------------------------------------
// EMA smear on K + PE add, output fp16
// ---------------------------------------------------------------------------
__global__ void smear_kernel(const float* __restrict__ alpha) {
    int idx = blockIdx.x * blockDim.x + threadIdx.x;
    int dk = idx & 63;
    int s  = (idx >> 6) & 2047;
    int h  = (idx >> 17) & 15;
    float kc = g_Kraw[idx];
    float v;
    if (s == 0) {
        v = kc;
    } else {
        float a = 1.0f / (1.0f + expf(-alpha[h * 2047 + (s - 1)]));
        v = a * kc + (1.0f - a) * g_Kraw[idx - 64];
    }
    v += g_PE[s * 64 + dk];
    g_Kh[idx] = __float2half_rn(v);
}

// ---------------------------------------------------------------------------
// Causal flash attention, fp16 HMMA. BM=128 (8 warps, 256 thr), BN=64.
// 3-stage KV ring, one barrier per tile. Global heavy-first grid order:
// bh on blockIdx.x (fastest), qt on blockIdx.y.
// ---------------------------------------------------------------------------
#define ASTR 144
#define AMAT (64 * ASTR)    // 9216
#define KVSTG (2 * AMAT)    // 18432 per stage
#define ATT_SMEM (3 * KVSTG) // 55296

__global__ __launch_bounds__(256, 2) void attn_mma() {
    extern __shared__ __align__(16) char asm_dyn[];
    uint32_t sb = smem_u32(asm_dyn);

    int t = threadIdx.x, lane = t & 31, w = t >> 5;   // w = 0..7
    int qt = 15 - (int)blockIdx.y;          // heavy tiles first (globally)
    int qb = qt * 128;
    int bh = blockIdx.x;
    size_t base = (size_t)bh * SS * DKK;

    // ---- stage Q tile into stage-0 region, extract frags ----
    {
        const char* qsrc = (const char*)(g_Qh + base);
#pragma unroll
        for (int q = 0; q < 4; q++) {
            int idx = t * 4 + q;
            int r   = idx >> 3;
            int c   = idx & 7;
            CPA16(sb + r * ASTR + c * 16,
                  qsrc + ((size_t)(qb + r) * 64 + c * 8) * 2);
        }
        CPA_COMMIT(); CPA_WAIT0();
        __syncthreads();
    }

    uint32_t qF[4][4];
    {
        int ar = w * 16 + (lane & 15);
#pragma unroll
        for (int k = 0; k < 4; k++) {
            uint32_t acol = (uint32_t)(k * 32 + (lane >> 4) * 16);
            ldsm_x4(qF[k], sb + ar * ASTR + acol);
        }
    }
    __syncthreads();   // Q frags extracted before stage 0 reused for KV

    float o[8][4];
    float m2[2], lsum[2];
#pragma unroll
    for (int j = 0; j < 8; j++)
#pragma unroll
        for (int u = 0; u < 4; u++) o[j][u] = 0.0f;
    m2[0] = m2[1] = -1e30f;
    lsum[0] = lsum[1] = 0.0f;

    const char* kvsrc[2] = {(const char*)(g_Kh + base), (const char*)(g_Vh + base)};

    auto load_kv = [&](int tile, int st) {
        uint32_t stb = sb + st * KVSTG;
        int kb = tile * 64;
#pragma unroll
        for (int q = 0; q < 4; q++) {
            int idx = t * 4 + q;
            int mat = idx >> 9;
            int r   = (idx >> 3) & 63;
            int c   = idx & 7;
            CPA16(stb + mat * AMAT + r * ASTR + c * 16,
                  kvsrc[mat] + ((size_t)(kb + r) * 64 + c * 8) * 2);
        }
        CPA_COMMIT();
    };

    int r0 = (lane >> 2);
    int ntiles = 2 * qt + 2;

    load_kv(0, 0);
    if (ntiles > 1) load_kv(1, 1);

    int st = 0;
    for (int tile = 0; tile < ntiles; tile++) {
        int kb = tile * 64;
        if (tile + 1 < ntiles) { CPA_WAIT1(); } else { CPA_WAIT0(); }
        __syncthreads();           // tile data ready AND all warps done with stage of tile-1
        if (tile + 2 < ntiles) {
            int s2 = st + 2; if (s2 >= 3) s2 -= 3;   // stage of tile-1 (free now)
            load_kv(tile + 2, s2);
        }

        uint32_t stb = sb + st * KVSTG;
        bool active = (kb <= qb + w * 16 + 15);   // skip fully-masked tiles

        if (active) {
            // ---- S = Q K^T ----
            float s[8][4];
#pragma unroll
            for (int j = 0; j < 8; j++)
#pragma unroll
                for (int u = 0; u < 4; u++) s[j][u] = 0.0f;

            {
                int b_row = (lane & 7) + 8 * (lane >> 4);
#pragma unroll
                for (int k = 0; k < 4; k++) {
                    uint32_t bcol = (uint32_t)((k * 16 + 8 * ((lane >> 3) & 1)) * 2);
                    uint32_t kF[8][2];
#pragma unroll
                    for (int tp = 0; tp < 4; tp++) {
                        uint32_t off = (uint32_t)((b_row + 16 * tp) * ASTR) + bcol;
                        ldsm_x4(&kF[2 * tp][0], stb + 0 * AMAT + off);
                    }
#pragma unroll
                    for (int j = 0; j < 8; j++) mma_f16(s[j], qF[k], kF[j]);
                }
            }

            // ---- mask (global row/col) ----
            if (kb + 63 > qb + w * 16) {
#pragma unroll
                for (int j = 0; j < 8; j++)
#pragma unroll
                    for (int u = 0; u < 4; u++) {
                        int row = qb + w * 16 + r0 + 8 * (u >> 1);
                        int col = kb + j * 8 + 2 * (lane & 3) + (u & 1);
                        if (col > row) s[j][u] = -1e30f;
                    }
            }

            // ---- online softmax (base 2), per row half, lazy rescale ----
#pragma unroll
            for (int h = 0; h < 2; h++) {
                float mx = -1e30f;
#pragma unroll
                for (int j = 0; j < 8; j++) {
                    mx = fmaxf(mx, s[j][2 * h + 0]);
                    mx = fmaxf(mx, s[j][2 * h + 1]);
                }
                mx = fmaxf(mx, __shfl_xor_sync(0xffffffffu, mx, 1));
                mx = fmaxf(mx, __shfl_xor_sync(0xffffffffu, mx, 2));
                if (mx > m2[h]) {
                    // max moved: rescale previous state (corr == 1 otherwise)
                    float corr = ex2(m2[h] - mx);
                    m2[h] = mx;
                    lsum[h] *= corr;
#pragma unroll
                    for (int j = 0; j < 8; j++) {
                        o[j][2 * h + 0] *= corr;
                        o[j][2 * h + 1] *= corr;
                    }
                }
                float mnew = m2[h];
                float rs = 0.0f;
#pragma unroll
                for (int j = 0; j < 8; j++) {
                    float p0 = ex2(s[j][2 * h + 0] - mnew);
                    float p1 = ex2(s[j][2 * h + 1] - mnew);
                    s[j][2 * h + 0] = p0;
                    s[j][2 * h + 1] = p1;
                    rs += p0 + p1;
                }
                lsum[h] += rs;
            }

            // ---- P fragments (C->A remap, fp16) ----
            uint32_t pF[4][4];
#pragma unroll
            for (int kk = 0; kk < 4; kk++) {
                int j = 2 * kk;
#pragma unroll
                for (int q = 0; q < 4; q++) {
                    int jj = j + (q >> 1);
                    __half2 hp = __floats2half2_rn(s[jj][(q & 1) * 2 + 0],
                                                   s[jj][(q & 1) * 2 + 1]);
                    pF[kk][q] = *(uint32_t*)&hp;
                }
            }

            // ---- O += P V, V via ldmatrix.trans (mat 1) ----
            {
                int vrow = (lane & 7) + 8 * ((lane >> 3) & 1);
                uint32_t vcol = (uint32_t)(16 * (lane >> 4));
#pragma unroll
                for (int kk = 0; kk < 4; kk++) {
                    uint32_t vF[8][2];
#pragma unroll
                    for (int jj = 0; jj < 4; jj++) {
                        uint32_t off = (uint32_t)((kk * 16 + vrow) * ASTR) + (uint32_t)(jj * 32) + vcol;
                        ldsm_x4_t(&vF[2 * jj][0], stb + 1 * AMAT + off);
                    }
#pragma unroll
                    for (int j = 0; j < 8; j++) mma_f16(o[j], pF[kk], vF[j]);
                }
            }
        }

        st++; if (st == 3) st = 0;
    }

    // ---- epilogue: normalize, fp16, store ----
#pragma unroll
    for (int h = 0; h < 2; h++) {
        lsum[h] += __shfl_xor_sync(0xffffffffu, lsum[h], 1);
        lsum[h] += __shfl_xor_sync(0xffffffffu, lsum[h], 2);
        lsum[h] = 1.0f / lsum[h];
    }

    int b = bh >> 4, hh = bh & 15;
#pragma unroll
    for (int j = 0; j < 8; j++) {
        int dk = j * 8 + 2 * (lane & 3);
#pragma unroll
        for (int h = 0; h < 2; h++) {
            int srow = qb + w * 16 + r0 + 8 * h;
            float f0 = o[j][2 * h + 0] * lsum[h];
            float f1 = o[j][2 * h + 1] * lsum[h];
            size_t off = ((size_t)(b * SS + srow) * DD + hh * 64 + dk) >> 1;
            ((__half2*)g_Ah)[off] = __floats2half2_rn(f0, f1);
        }
    }
}

// ---------------------------------------------------------------------------
// Output projection GEMM: Y = attn @ Wo^T + X
// ---------------------------------------------------------------------------
__global__ __launch_bounds__(128, 2) void oproj_mma(const float* __restrict__ X) {
    extern __shared__ char dyn[];
    float acc[4][8][4];

    int m0 = blockIdx.y * 128;
    int n0 = blockIdx.x * 128;

    mma_gemm(g_Ah + (size_t)m0 * 1024, g_Woh + (size_t)n0 * 1024, dyn, acc);

    int t = threadIdx.x, lane = t & 31, wid = t >> 5;
    int wm = wid & 1, wn = wid >> 1;
#pragma unroll
    for (int tm = 0; tm < 4; tm++)
#pragma unroll
        for (int tn = 0; tn < 8; tn++) {
            int c = n0 + wn * 64 + tn * 8 + (lane & 3) * 2;
#pragma unroll
            for (int half = 0; half < 2; half++) {
                int m = m0 + wm * 64 + tm * 16 + (lane >> 2) + 8 * half;
                float2 xr = *(const float2*)&X[(size_t)m * 1024 + c];
                float2 v;
                v.x = acc[tm][tn][2 * half + 0] + xr.x;
                v.y = acc[tm][tn][2 * half + 1] + xr.y;
                *(float2*)&g_Y[(size_t)m * 1024 + c] = v;
            }
        }
}

// ---------------------------------------------------------------------------
// LayerNorm over D=1024 per row
// ---------------------------------------------------------------------------
__global__ void ln_kernel(const float* __restrict__ gamma,
                          const float* __restrict__ beta,
                          float* __restrict__ out)
{
    int row = blockIdx.x;
    int t   = threadIdx.x;
    const float* y = g_Y + (size_t)row * 1024;

    float x[4];
    float s = 0.0f;
#pragma unroll
    for (int u = 0; u < 4; u++) { x[u] = y[t + 256 * u]; s += x[u]; }

    __shared__ float red[32];
#pragma unroll
    for (int off = 16; off; off >>= 1) s += __shfl_xor_sync(0xffffffffu, s, off);
    if ((t & 31) == 0) red[t >> 5] = s;
    __syncthreads();
    if (t == 0) {
        float tot = 0.0f;
        for (int w = 0; w < 8; w++) tot += red[w];
        red[8] = tot;
    }
    __syncthreads();
    float mean = red[8] * (1.0f / 1024.0f);

    float vs = 0.0f;
#pragma unroll
    for (int u = 0; u < 4; u++) { float d = x[u] - mean; vs += d * d; }
#pragma unroll
    for (int off = 16; off; off >>= 1) vs += __shfl_xor_sync(0xffffffffu, vs, off);
    if ((t & 31) == 0) red[16 + (t >> 5)] = vs;
    __syncthreads();
    if (t == 0) {
        float tot = 0.0f;
        for (int w = 0; w < 8; w++) tot += red[16 + w];
        red[24] = tot;
    }
    __syncthreads();
    float var  = red[24] * (1.0f / 1024.0f);
    float rstd = rsqrtf(var + 1e-5f);

#pragma unroll
    for (int u = 0; u < 4; u++) {
        int c = t + 256 * u;
        out[(size_t)row * 1024 + c] = (x[u] - mean) * rstd * gamma[c] + beta[c];
    }
}

// ---------------------------------------------------------------------------
extern "C" void kernel_launch(void* const* d_in, const int* in_sizes, int n_in,
                              void* d_out, int out_size)
{
    const float* X     = (const float*)d_in[0];
    const float* Wq    = (const float*)d_in[1];
    const float* Wk    = (const float*)d_in[2];
    const float* Wv    = (const float*)d_in[3];
    const float* Wo    = (const float*)d_in[4];
    const float* alpha = (const float*)d_in[5];
    const float* lns   = (const float*)d_in[6];
    const float* lnb   = (const float*)d_in[7];
    float* out = (float*)d_out;

    static int attr_set = 0;
    if (!attr_set) {
        cudaFuncSetAttribute(qkv_mma,   cudaFuncAttributeMaxDynamicSharedMemorySize, DYN_SMEM);
        cudaFuncSetAttribute(oproj_mma, cudaFuncAttributeMaxDynamicSharedMemorySize, DYN_SMEM);
        cudaFuncSetAttribute(attn_mma,  cudaFuncAttributeMaxDynamicSharedMemorySize, ATT_SMEM);
        attr_set = 1;
    }

    prep_kernel<<<8704, 256>>>(X, Wq, Wk, Wv, Wo);                 // 1
    qkv_mma<<<dim3(8, 32, 3), 128, DYN_SMEM>>>();                  // 2
    smear_kernel<<<(MM * DD) / 256, 256>>>(alpha);                 // 3
    attn_mma<<<dim3(32, 16), 256, ATT_SMEM>>>();                   // 4
    oproj_mma<<<dim3(8, 32), 128, DYN_SMEM>>>(X);                  // 5
    ln_kernel<<<MM, 256>>>(lns, lnb, out);                         // 6
}